// round 15
// baseline (speedup 1.0000x reference)
#include <cuda_runtime.h>
#include <math.h>
#include <stdint.h>

#define M_TOK 12608
#define C_DIM 768
#define H_DIM 3072

// ---------------- scratch (device globals; no allocation allowed) ----------------
__device__ int8_t  g_qa[(size_t)M_TOK * C_DIM];
__device__ int8_t  g_qw1[(size_t)H_DIM * C_DIM];
__device__ int8_t  g_qw2[(size_t)C_DIM * H_DIM];
__device__ int8_t  g_qh[(size_t)M_TOK * H_DIM];
__device__ float   g_h[(size_t)M_TOK * H_DIM];      // g = gelu(h)
__device__ uint32_t g_wl[(size_t)M_TOK * H_DIM / 8];
__device__ unsigned int g_wlcnt;
__device__ float   g_xminC[C_DIM];
__device__ float   g_xmaxC[C_DIM];
__device__ float   g_w1cmax[C_DIM];
__device__ float   g_cs[C_DIM];
__device__ float   g_sw1[H_DIM];
__device__ int     g_colsum1[H_DIM];
__device__ float   g_sw2[C_DIM];
__device__ float   g_sx;
__device__ float   g_zp;
__device__ int     g_k128;
__device__ float   g_habs;   // approx (exact-h gelu max)
__device__ float   g_habs2;  // chain-exact (repaired candidates)
__device__ float   g_omin, g_omax;

// ---------------- atomic float min/max ----------------
__device__ __forceinline__ void atomicMaxF(float* a, float v) {
    if (v >= 0.f) atomicMax((int*)a, __float_as_int(v));
    else          atomicMin((unsigned int*)a, __float_as_uint(v));
}
__device__ __forceinline__ void atomicMinF(float* a, float v) {
    if (v >= 0.f) atomicMin((int*)a, __float_as_int(v));
    else          atomicMax((unsigned int*)a, __float_as_uint(v));
}

// ---------------- warp-level int8 MMA + ldmatrix + LDS (baseline PTX) ----------------
__device__ __forceinline__ void mma_s8(int* c, const uint32_t* a, const uint32_t* b) {
    asm volatile(
        "mma.sync.aligned.m16n8k32.row.col.s32.s8.s8.s32 "
        "{%0,%1,%2,%3}, {%4,%5,%6,%7}, {%8,%9}, {%0,%1,%2,%3};"
        : "+r"(c[0]), "+r"(c[1]), "+r"(c[2]), "+r"(c[3])
        : "r"(a[0]), "r"(a[1]), "r"(a[2]), "r"(a[3]), "r"(b[0]), "r"(b[1]));
}
__device__ __forceinline__ void ldsm_x4(uint32_t& r0, uint32_t& r1, uint32_t& r2,
                                        uint32_t& r3, uint32_t addr) {
    asm volatile("ldmatrix.sync.aligned.m8n8.x4.shared.b16 {%0,%1,%2,%3}, [%4];"
                 : "=r"(r0), "=r"(r1), "=r"(r2), "=r"(r3) : "r"(addr));
}
__device__ __forceinline__ uint4 lds128(uint32_t addr) {
    uint4 v;
    asm volatile("ld.shared.v4.u32 {%0,%1,%2,%3}, [%4];"
                 : "=r"(v.x), "=r"(v.y), "=r"(v.z), "=r"(v.w) : "r"(addr));
    return v;
}

// ---------------- cp.async helpers ----------------
__device__ __forceinline__ void cp16(uint32_t saddr, const void* g, uint32_t sz) {
    asm volatile("cp.async.cg.shared.global [%0], [%1], 16, %2;"
                 :: "r"(saddr), "l"(__cvta_generic_to_global(g)), "r"(sz));
}
__device__ __forceinline__ void cp_commit() {
    asm volatile("cp.async.commit_group;");
}
__device__ __forceinline__ void cp_wait0() {
    asm volatile("cp.async.wait_group 0;");
}

// ---------------- XLA f32 erf (ErfImpl32) ----------------
__device__ __forceinline__ float xla_erf(float x) {
    float w = fminf(fmaxf(x, -4.0f), 4.0f);
    float s = __fmul_rn(w, w);
    float num = -2.72614225801306e-10f;
    num = __fadd_rn(__fmul_rn(num, s),  2.77068142495902e-08f);
    num = __fadd_rn(__fmul_rn(num, s), -2.10102402082508e-06f);
    num = __fadd_rn(__fmul_rn(num, s), -5.69250639462346e-05f);
    num = __fadd_rn(__fmul_rn(num, s), -7.34990630326855e-04f);
    num = __fadd_rn(__fmul_rn(num, s), -2.95459980854025e-03f);
    num = __fadd_rn(__fmul_rn(num, s), -1.60960333262415e-02f);
    float den = -1.45660718464996e-05f;
    den = __fadd_rn(__fmul_rn(den, s), -2.13374055278905e-04f);
    den = __fadd_rn(__fmul_rn(den, s), -1.68282697438203e-03f);
    den = __fadd_rn(__fmul_rn(den, s), -7.37332916720468e-03f);
    den = __fadd_rn(__fmul_rn(den, s), -1.42647390514189e-02f);
    return __fdiv_rn(__fmul_rn(w, num), den);
}
__device__ __forceinline__ float xla_gelu(float x) {
    float u = __fdiv_rn(x, 1.4142135623730951f);
    float e = xla_erf(u);
    return __fmul_rn(__fmul_rn(x, __fadd_rn(e, 1.0f)), 0.5f);
}

// ---------------- init ----------------
__global__ void k_init() {
    int t = blockIdx.x * blockDim.x + threadIdx.x;
    if (t < C_DIM) {
        g_xminC[t]  = INFINITY;
        g_xmaxC[t]  = -INFINITY;
        g_w1cmax[t] = 0.f;
    }
    if (t == 0) {
        g_habs = 0.f; g_habs2 = 0.f; g_wlcnt = 0u;
        g_omin = INFINITY; g_omax = -INFINITY;
    }
}

// ---------------- merged per-channel stats: z=0 -> x min/max, z=1 -> |w1| max ----------------
__global__ void k_stats(const float* __restrict__ x, const float* __restrict__ w1) {
    int c = blockIdx.x * 256 + threadIdx.x;
    if (blockIdx.z == 0) {
        int m0 = blockIdx.y * 197;
        float mn = INFINITY, mx = -INFINITY;
        const float* p = x + (size_t)m0 * C_DIM + c;
        #pragma unroll 4
        for (int i = 0; i < 197; ++i) {
            float v = p[(size_t)i * C_DIM];
            mn = fminf(mn, v); mx = fmaxf(mx, v);
        }
        atomicMinF(&g_xminC[c], mn);
        atomicMaxF(&g_xmaxC[c], mx);
    } else {
        if (blockIdx.y >= 12) return;
        int h0 = blockIdx.y * 256;
        float mx = 0.f;
        const float* p = w1 + (size_t)h0 * C_DIM + c;
        #pragma unroll 4
        for (int i = 0; i < 256; ++i)
            mx = fmaxf(mx, fabsf(p[(size_t)i * C_DIM]));
        atomicMax((int*)&g_w1cmax[c], __float_as_int(mx));
    }
}

// ---------------- cs + activation scale/zp ----------------
__global__ void k_scalars() {
    __shared__ float smn[256], smx[256];
    int tid = threadIdx.x;
    const float LN2F = 0.6931471805599453f;
    float mn = INFINITY, mx = -INFINITY;
    for (int c = tid; c < C_DIM; c += 256) {
        float xlo = g_xminC[c], xhi = g_xmaxC[c];
        float gmax = fmaxf(fabsf(xlo), fabsf(xhi));
        float mw = g_w1cmax[c];
        float csr = __fdiv_rn(sqrtf(gmax), sqrtf(mw));
        float y = floorf(__fdiv_rn(logf(csr), LN2F));
        float p = exp2f(y);
        float cs = (__fsub_rn(csr, p) > __fsub_rn(__fmul_rn(2.f, p), csr)) ? 2.f * p : p;
        g_cs[c] = cs;
        mn = fminf(mn, __fdiv_rn(xlo, cs));
        mx = fmaxf(mx, __fdiv_rn(xhi, cs));
    }
    smn[tid] = mn; smx[tid] = mx;
    __syncthreads();
    for (int s = 128; s > 0; s >>= 1) {
        if (tid < s) {
            smn[tid] = fminf(smn[tid], smn[tid + s]);
            smx[tid] = fmaxf(smx[tid], smx[tid + s]);
        }
        __syncthreads();
    }
    if (tid == 0) {
        float xmn = fminf(smn[0], 0.f);
        float xmx = fmaxf(smx[0], 0.f);
        float s = fmaxf(__fdiv_rn(__fsub_rn(xmx, xmn), 255.f), 1e-8f);
        float zp = rintf(__fdiv_rn(-xmn, s));
        g_sx = s; g_zp = zp; g_k128 = 128 - (int)zp;
    }
}

// ---------------- quantize x -> s8 (q - 128), vectorized x4 ----------------
__global__ void k_quant_x(const float* __restrict__ x) {
    size_t i4 = (size_t)blockIdx.x * 256 + threadIdx.x;
    if (i4 >= (size_t)M_TOK * C_DIM / 4) return;
    int c = (int)((i4 * 4) % C_DIM);
    float s = g_sx, zp = g_zp;
    const float4 v = reinterpret_cast<const float4*>(x)[i4];
    char4 o;
    float t, q;
    t = __fdiv_rn(v.x, g_cs[c + 0]);
    q = fminf(fmaxf(__fadd_rn(rintf(__fdiv_rn(t, s)), zp), 0.f), 255.f);
    o.x = (int8_t)((int)q - 128);
    t = __fdiv_rn(v.y, g_cs[c + 1]);
    q = fminf(fmaxf(__fadd_rn(rintf(__fdiv_rn(t, s)), zp), 0.f), 255.f);
    o.y = (int8_t)((int)q - 128);
    t = __fdiv_rn(v.z, g_cs[c + 2]);
    q = fminf(fmaxf(__fadd_rn(rintf(__fdiv_rn(t, s)), zp), 0.f), 255.f);
    o.z = (int8_t)((int)q - 128);
    t = __fdiv_rn(v.w, g_cs[c + 3]);
    q = fminf(fmaxf(__fadd_rn(rintf(__fdiv_rn(t, s)), zp), 0.f), 255.f);
    o.w = (int8_t)((int)q - 128);
    reinterpret_cast<char4*>(g_qa)[i4] = o;
}

// ---------------- merged weight quant ----------------
__global__ void k_quant_w(const float* __restrict__ w1, const float* __restrict__ w2) {
    __shared__ float red[256];
    __shared__ int   redi[256];
    int tid = threadIdx.x;
    if (blockIdx.x < H_DIM) {
        int j = blockIdx.x;
        const float* row = w1 + (size_t)j * C_DIM;
        float mx = 0.f;
        for (int c = tid; c < C_DIM; c += 256)
            mx = fmaxf(mx, fabsf(__fmul_rn(row[c], g_cs[c])));
        red[tid] = mx; __syncthreads();
        for (int s = 128; s > 0; s >>= 1) {
            if (tid < s) red[tid] = fmaxf(red[tid], red[tid + s]);
            __syncthreads();
        }
        float sc = fmaxf(__fdiv_rn(red[0], 127.f), 1e-8f);
        __syncthreads();
        int csum = 0;
        for (int c = tid; c < C_DIM; c += 256) {
            float ws = __fmul_rn(row[c], g_cs[c]);
            float q = rintf(__fdiv_rn(ws, sc));
            q = fminf(fmaxf(q, -128.f), 127.f);
            int qi = (int)q;
            g_qw1[(size_t)j * C_DIM + c] = (int8_t)qi;
            csum += qi;
        }
        redi[tid] = csum; __syncthreads();
        for (int s = 128; s > 0; s >>= 1) {
            if (tid < s) redi[tid] += redi[tid + s];
            __syncthreads();
        }
        if (tid == 0) { g_colsum1[j] = redi[0]; g_sw1[j] = sc; }
    } else {
        int j = blockIdx.x - H_DIM;
        const float* row = w2 + (size_t)j * H_DIM;
        float mx = 0.f;
        for (int c = tid; c < H_DIM; c += 256)
            mx = fmaxf(mx, fabsf(row[c]));
        red[tid] = mx; __syncthreads();
        for (int s = 128; s > 0; s >>= 1) {
            if (tid < s) red[tid] = fmaxf(red[tid], red[tid + s]);
            __syncthreads();
        }
        float sc = fmaxf(__fdiv_rn(red[0], 127.f), 1e-8f);
        __syncthreads();
        for (int c = tid; c < H_DIM; c += 256) {
            float q = rintf(__fdiv_rn(row[c], sc));
            q = fminf(fmaxf(q, -128.f), 127.f);
            g_qw2[(size_t)j * H_DIM + c] = (int8_t)(int)q;
        }
        if (tid == 0) g_sw2[j] = sc;
    }
}

#define ROW_W 36            // smem row stride in words (128B data + 16B pad)
#define STG_WORDS (128 * ROW_W)
#define NSTAGE 2
#define DYN_BYTES (2 * NSTAGE * STG_WORDS * 4)   // 73728

// =====================================================================
// Hybrid 128B chunk: MMA cols 0..39 (4 k32 steps, 40 MMA/warp) +
// dp4a cols 40..63 in two 64B half-passes (aw[16] pattern preserved).
// Integer accumulation -> bit-identical to R11/R14.
// =====================================================================
__device__ __forceinline__ void dp4a_half(uint32_t aBase, uint32_t bBase,
                                          int warpM, int warpN, int lane,
                                          uint32_t off, int (&accd)[24]) {
    uint32_t aw[16];
    {
        uint32_t ar = aBase + 4u * (uint32_t)((warpM * 32 + lane) * ROW_W) + off;
        #pragma unroll
        for (int s = 0; s < 4; ++s) {
            uint4 v = lds128(ar + 16u * s);
            aw[4 * s] = v.x; aw[4 * s + 1] = v.y; aw[4 * s + 2] = v.z; aw[4 * s + 3] = v.w;
        }
    }
    #pragma unroll
    for (int cc = 0; cc < 24; ++cc) {
        uint32_t br = bBase + 4u * (uint32_t)((warpN * 64 + 40 + cc) * ROW_W) + off;
        int a0 = accd[cc];
        #pragma unroll
        for (int s = 0; s < 4; ++s) {
            uint4 bv = lds128(br + 16u * s);
            a0 = __dp4a((int)aw[4 * s],     (int)bv.x, a0);
            a0 = __dp4a((int)aw[4 * s + 1], (int)bv.y, a0);
            a0 = __dp4a((int)aw[4 * s + 2], (int)bv.z, a0);
            a0 = __dp4a((int)aw[4 * s + 3], (int)bv.w, a0);
        }
        accd[cc] = a0;
    }
}

__device__ __forceinline__ void hyb_chunk(uint32_t aBase, uint32_t bBase,
                                          int warpM, int warpN, int lane,
                                          int rA, int cA, int rB, int cB,
                                          int (&acc)[2][5][4], int (&accd)[24]) {
    #pragma unroll
    for (int ks = 0; ks < 4; ++ks) {
        uint32_t a[2][4];
        #pragma unroll
        for (int mt = 0; mt < 2; ++mt) {
            uint32_t ad = aBase + 4u * (uint32_t)((warpM * 32 + mt * 16 + rA) * ROW_W + ks * 8 + cA);
            ldsm_x4(a[mt][0], a[mt][1], a[mt][2], a[mt][3], ad);
        }
        uint32_t b[6][2];
        #pragma unroll
        for (int np = 0; np < 3; ++np) {
            uint32_t bd = bBase + 4u * (uint32_t)((warpN * 64 + np * 16 + rB) * ROW_W + ks * 8 + cB);
            ldsm_x4(b[2 * np][0], b[2 * np][1], b[2 * np + 1][0], b[2 * np + 1][1], bd);
        }
        #pragma unroll
        for (int mt = 0; mt < 2; ++mt)
            #pragma unroll
            for (int nt = 0; nt < 5; ++nt)
                mma_s8(acc[mt][nt], a[mt], b[nt]);
    }
    dp4a_half(aBase, bBase, warpM, warpN, lane, 0u, accd);
    dp4a_half(aBase, bBase, warpM, warpN, lane, 64u, accd);
}

// staging of one 128B chunk: thread copies 64B of its row half
__device__ __forceinline__ void stage_chunk(uint32_t sa, uint32_t sb,
                                            const int8_t* ga, const int8_t* gb,
                                            uint32_t asz) {
    cp16(sa, ga, asz);       cp16(sa + 16, ga + 16, asz);
    cp16(sa + 32, ga + 32, asz); cp16(sa + 48, ga + 48, asz);
    cp16(sb, gb, 16u);       cp16(sb + 16, gb + 16, 16u);
    cp16(sb + 32, gb + 32, 16u); cp16(sb + 48, gb + 48, 16u);
}

// =====================================================================
// GEMM1: hybrid IMMA+dp4a, 128B chunks, 2-stage cp.async, occ=2.
// =====================================================================
__global__ __launch_bounds__(256, 2) void k_gemm1_tc(const float* __restrict__ b1) {
    extern __shared__ uint32_t dyn[];
    __shared__ float s_sw1[128], s_b1[128];
    __shared__ int   s_cs1[128];
    __shared__ float red[256];

    const int tid = threadIdx.x;
    const int wid = tid >> 5, lane = tid & 31;
    const int grp = lane >> 2, tg = lane & 3;
    const int warpM = wid & 3, warpN = wid >> 2;
    const int bx = blockIdx.x, by = blockIdx.y;
    const int iA = lane >> 3;
    const int rA = ((iA & 1) << 3) + (lane & 7), cA = (iA >> 1) << 2;
    const int rB = ((iA >> 1) << 3) + (lane & 7), cB = (iA & 1) << 2;

    if (tid < 128) {
        s_sw1[tid] = g_sw1[bx * 128 + tid];
        s_b1[tid]  = b1[bx * 128 + tid];
        s_cs1[tid] = g_colsum1[bx * 128 + tid];
    }

    int acc[2][5][4];
    int accd[24];
    #pragma unroll
    for (int mt = 0; mt < 2; ++mt)
        #pragma unroll
        for (int nt = 0; nt < 5; ++nt)
            #pragma unroll
            for (int r = 0; r < 4; ++r) acc[mt][nt][r] = 0;
    #pragma unroll
    for (int c = 0; c < 24; ++c) accd[c] = 0;

    const uint32_t dynAddr = (uint32_t)__cvta_generic_to_shared(dyn);
    const int srow = tid >> 1, shalf = tid & 1;
    const int growA = by * 128 + srow;
    const bool aval = (growA < M_TOK);
    const uint32_t asz = aval ? 16u : 0u;
    const int8_t* gA = g_qa + (size_t)(aval ? growA : 0) * C_DIM + shalf * 64;
    const int8_t* gB = g_qw1 + (size_t)(bx * 128 + srow) * C_DIM + shalf * 64;
    const uint32_t stOff = (uint32_t)((srow * ROW_W + shalf * 16) * 4);

    const int NCH = C_DIM / 128;  // 6
    {
        uint32_t sa = dynAddr + stOff;
        uint32_t sb = dynAddr + (uint32_t)(NSTAGE * STG_WORDS * 4) + stOff;
        stage_chunk(sa, sb, gA, gB, asz);
        cp_commit();
    }

    for (int kc = 0; kc < NCH; ++kc) {
        const int p = kc & 1;
        cp_wait0();
        __syncthreads();
        if (kc + 1 < NCH) {
            const int q = p ^ 1;
            uint32_t sa = dynAddr + (uint32_t)(q * STG_WORDS * 4) + stOff;
            uint32_t sb = dynAddr + (uint32_t)((NSTAGE + q) * STG_WORDS * 4) + stOff;
            stage_chunk(sa, sb, gA + (kc + 1) * 128, gB + (kc + 1) * 128, asz);
        }
        cp_commit();
        hyb_chunk(dynAddr + (uint32_t)(p * STG_WORDS * 4),
                  dynAddr + (uint32_t)((NSTAGE + p) * STG_WORDS * 4),
                  warpM, warpN, lane, rA, cA, rB, cB, acc, accd);
    }

    const double sxd = (double)g_sx;
    const int k128 = g_k128;
    float lmax = 0.f;
    #pragma unroll
    for (int mt = 0; mt < 2; ++mt) {
        int r0 = by * 128 + warpM * 32 + mt * 16 + grp;
        #pragma unroll
        for (int nt = 0; nt < 5; ++nt) {
            int colL = warpN * 64 + nt * 8 + tg * 2;
            size_t gcol = (size_t)bx * 128 + colL;
            double coef0 = sxd * (double)s_sw1[colL];
            double coef1 = sxd * (double)s_sw1[colL + 1];
            int corr0 = k128 * s_cs1[colL];
            int corr1 = k128 * s_cs1[colL + 1];
            double bb0 = (double)s_b1[colL], bb1 = (double)s_b1[colL + 1];
            #pragma unroll
            for (int hh = 0; hh < 2; ++hh) {
                int row = r0 + hh * 8;
                if (row < M_TOK) {
                    float h0 = (float)(coef0 * (double)(acc[mt][nt][hh * 2] + corr0) + bb0);
                    float h1 = (float)(coef1 * (double)(acc[mt][nt][hh * 2 + 1] + corr1) + bb1);
                    float g0 = xla_gelu(h0);
                    float g1 = xla_gelu(h1);
                    size_t o = (size_t)row * H_DIM + gcol;
                    g_h[o] = g0; g_h[o + 1] = g1;
                    lmax = fmaxf(lmax, fmaxf(fabsf(g0), fabsf(g1)));
                }
            }
        }
    }
    {
        int rowd = by * 128 + warpM * 32 + lane;
        if (rowd < M_TOK) {
            #pragma unroll
            for (int q6 = 0; q6 < 6; ++q6) {
                float4 gw;
                #pragma unroll
                for (int e = 0; e < 4; ++e) {
                    int cc = q6 * 4 + e;
                    int colL = warpN * 64 + 40 + cc;
                    double coef = sxd * (double)s_sw1[colL];
                    int corr = k128 * s_cs1[colL];
                    double bb = (double)s_b1[colL];
                    float h = (float)(coef * (double)(accd[cc] + corr) + bb);
                    float g = xla_gelu(h);
                    (&gw.x)[e] = g;
                    lmax = fmaxf(lmax, fabsf(g));
                }
                size_t o = (size_t)rowd * H_DIM + bx * 128 + warpN * 64 + 40 + q6 * 4;
                *reinterpret_cast<float4*>(&g_h[o]) = gw;
            }
        }
    }
    red[tid] = lmax; __syncthreads();
    for (int s = 128; s > 0; s >>= 1) {
        if (tid < s) red[tid] = fmaxf(red[tid], red[tid + s]);
        __syncthreads();
    }
    if (tid == 0) atomicMaxF(&g_habs, red[0]);
}

// =====================================================================
// Fused flag + provisional quant.
// =====================================================================
__global__ void k_flagq() {
    size_t i4 = (size_t)blockIdx.x * 256 + threadIdx.x;
    if (i4 >= (size_t)M_TOK * H_DIM / 4) return;
    const float4 g4 = reinterpret_cast<const float4*>(g_h)[i4];
    float gv[4] = { g4.x, g4.y, g4.z, g4.w };
    float habs = g_habs;
    float sh = fmaxf(__fdiv_rn(habs, 127.f), 1e-8f);
    float taumax = fmaxf(habs, 2.f) * 1.6e-5f;
    char4 o;
    #pragma unroll
    for (int t = 0; t < 4; ++t) {
        float g = gv[t];
        float r = __fdiv_rn(g, sh);
        float q = fminf(fmaxf(rintf(r), -128.f), 127.f);
        ((int8_t*)&o)[t] = (int8_t)(int)q;
        float hb = fmaxf(fabsf(g) + 0.25f, 3.0f);
        float tau = hb * 8e-6f + fabsf(g) * 4e-5f + 1e-6f;
        bool cand = fabsf(g) > habs - 2.f * taumax;
        float d = fabsf(r - rintf(r));
        bool near = fabsf(d - 0.5f) * sh < tau;
        if (near || cand) {
            unsigned int pos = atomicAdd(&g_wlcnt, 1u);
            if (pos < (unsigned int)((size_t)M_TOK * H_DIM / 8))
                g_wl[pos] = (uint32_t)(i4 * 4 + t);
        }
    }
    reinterpret_cast<char4*>(g_qh)[i4] = o;
}

// =====================================================================
// Chain-repair pass.
// =====================================================================
__global__ void k_chain(const float* __restrict__ b1) {
    unsigned int total = g_wlcnt;
    unsigned int cap = (unsigned int)((size_t)M_TOK * H_DIM / 8);
    if (total > cap) total = cap;
    const float sx = g_sx;
    const float k128f = (float)g_k128;
    float wmax = 0.f;
    for (unsigned int w = blockIdx.x * blockDim.x + threadIdx.x;
         w < total; w += gridDim.x * blockDim.x) {
        uint32_t idx = g_wl[w];
        int row = (int)(idx / H_DIM);
        int col = (int)(idx % H_DIM);
        const int8_t* ap = g_qa + (size_t)row * C_DIM;
        const int8_t* bp = g_qw1 + (size_t)col * C_DIM;
        const float sw = g_sw1[col];
        float acc = 0.f;
        for (int k = 0; k < C_DIM; k += 8) {
            int2 av = *reinterpret_cast<const int2*>(ap + k);
            int2 bv = *reinterpret_cast<const int2*>(bp + k);
            #pragma unroll
            for (int t = 0; t < 4; ++t) {
                float a = __fmul_rn((float)(int)(int8_t)(av.x >> (8 * t)) + k128f, sx);
                float b = __fmul_rn((float)(int)(int8_t)(bv.x >> (8 * t)), sw);
                acc = __fmaf_rn(a, b, acc);
            }
            #pragma unroll
            for (int t = 0; t < 4; ++t) {
                float a = __fmul_rn((float)(int)(int8_t)(av.y >> (8 * t)) + k128f, sx);
                float b = __fmul_rn((float)(int)(int8_t)(bv.y >> (8 * t)), sw);
                acc = __fmaf_rn(a, b, acc);
            }
        }
        float hv = __fadd_rn(acc, b1[col]);
        float gv = xla_gelu(hv);
        g_h[idx] = gv;
        wmax = fmaxf(wmax, fabsf(gv));
    }
    #pragma unroll
    for (int o = 16; o > 0; o >>= 1)
        wmax = fmaxf(wmax, __shfl_down_sync(0xFFFFFFFFu, wmax, o));
    if ((threadIdx.x & 31) == 0 && wmax > 0.f) atomicMaxF(&g_habs2, wmax);
}

// ---------------- re-quantize flagged elements with final sh2 ----------------
__global__ void k_fixq() {
    unsigned int total = g_wlcnt;
    unsigned int cap = (unsigned int)((size_t)M_TOK * H_DIM / 8);
    if (total > cap) total = cap;
    float sh = fmaxf(__fdiv_rn(g_habs2, 127.f), 1e-8f);
    for (unsigned int w = blockIdx.x * blockDim.x + threadIdx.x;
         w < total; w += gridDim.x * blockDim.x) {
        uint32_t idx = g_wl[w];
        float g = g_h[idx];
        float q = fminf(fmaxf(rintf(__fdiv_rn(g, sh)), -128.f), 127.f);
        g_qh[idx] = (int8_t)(int)q;
    }
}

// =====================================================================
// GEMM2: hybrid IMMA+dp4a, 128B chunks, 2-stage cp.async, occ=2.
// =====================================================================
__global__ __launch_bounds__(256, 2) void k_gemm2_mma(const float* __restrict__ b2,
                                                      float* __restrict__ out) {
    extern __shared__ uint32_t dyn[];
    __shared__ float s_sw2[128], s_b2[128];
    __shared__ float red[256];

    const int tid = threadIdx.x;
    const int wid = tid >> 5, lane = tid & 31;
    const int grp = lane >> 2, tg = lane & 3;
    const int warpM = wid & 3, warpN = wid >> 2;
    const int bx = blockIdx.x, by = blockIdx.y;
    const int iA = lane >> 3;
    const int rA = ((iA & 1) << 3) + (lane & 7), cA = (iA >> 1) << 2;
    const int rB = ((iA >> 1) << 3) + (lane & 7), cB = (iA & 1) << 2;

    if (tid < 128) {
        s_sw2[tid] = g_sw2[bx * 128 + tid];
        s_b2[tid]  = b2[bx * 128 + tid];
    }

    int acc[2][5][4];
    int accd[24];
    #pragma unroll
    for (int mt = 0; mt < 2; ++mt)
        #pragma unroll
        for (int nt = 0; nt < 5; ++nt)
            #pragma unroll
            for (int r = 0; r < 4; ++r) acc[mt][nt][r] = 0;
    #pragma unroll
    for (int c = 0; c < 24; ++c) accd[c] = 0;

    const uint32_t dynAddr = (uint32_t)__cvta_generic_to_shared(dyn);
    const int srow = tid >> 1, shalf = tid & 1;
    const int growA = by * 128 + srow;
    const bool aval = (growA < M_TOK);
    const uint32_t asz = aval ? 16u : 0u;
    const int8_t* gA = g_qh + (size_t)(aval ? growA : 0) * H_DIM + shalf * 64;
    const int8_t* gB = g_qw2 + (size_t)(bx * 128 + srow) * H_DIM + shalf * 64;
    const uint32_t stOff = (uint32_t)((srow * ROW_W + shalf * 16) * 4);

    const int NCH = H_DIM / 128;  // 24
    {
        uint32_t sa = dynAddr + stOff;
        uint32_t sb = dynAddr + (uint32_t)(NSTAGE * STG_WORDS * 4) + stOff;
        stage_chunk(sa, sb, gA, gB, asz);
        cp_commit();
    }

    for (int kc = 0; kc < NCH; ++kc) {
        const int p = kc & 1;
        cp_wait0();
        __syncthreads();
        if (kc + 1 < NCH) {
            const int q = p ^ 1;
            uint32_t sa = dynAddr + (uint32_t)(q * STG_WORDS * 4) + stOff;
            uint32_t sb = dynAddr + (uint32_t)((NSTAGE + q) * STG_WORDS * 4) + stOff;
            stage_chunk(sa, sb, gA + (kc + 1) * 128, gB + (kc + 1) * 128, asz);
        }
        cp_commit();
        hyb_chunk(dynAddr + (uint32_t)(p * STG_WORDS * 4),
                  dynAddr + (uint32_t)((NSTAGE + p) * STG_WORDS * 4),
                  warpM, warpN, lane, rA, cA, rB, cB, acc, accd);
    }

    const double shd = (double)fmaxf(__fdiv_rn(g_habs2, 127.f), 1e-8f);
    float lmin = INFINITY, lmax = -INFINITY;
    #pragma unroll
    for (int mt = 0; mt < 2; ++mt) {
        int r0 = by * 128 + warpM * 32 + mt * 16 + grp;
        #pragma unroll
        for (int nt = 0; nt < 5; ++nt) {
            int colL = warpN * 64 + nt * 8 + tg * 2;
            double coef0 = shd * (double)s_sw2[colL];
            double coef1 = shd * (double)s_sw2[colL + 1];
            float bb0 = s_b2[colL], bb1 = s_b2[colL + 1];
            size_t gcol = (size_t)bx * 128 + colL;
            #pragma unroll
            for (int h = 0; h < 2; ++h) {
                int row = r0 + h * 8;
                if (row < M_TOK) {
                    float d0 = (float)(coef0 * (double)acc[mt][nt][h * 2]);
                    float d1 = (float)(coef1 * (double)acc[mt][nt][h * 2 + 1]);
                    float v0 = __fadd_rn(d0, bb0);
                    float v1 = __fadd_rn(d1, bb1);
                    out[(size_t)row * C_DIM + gcol]     = v0;
                    out[(size_t)row * C_DIM + gcol + 1] = v1;
                    lmin = fminf(lmin, fminf(v0, v1));
                    lmax = fmaxf(lmax, fmaxf(v0, v1));
                }
            }
        }
    }
    {
        int rowd = by * 128 + warpM * 32 + lane;
        if (rowd < M_TOK) {
            #pragma unroll
            for (int q6 = 0; q6 < 6; ++q6) {
                float4 vw;
                #pragma unroll
                for (int e = 0; e < 4; ++e) {
                    int cc = q6 * 4 + e;
                    int colL = warpN * 64 + 40 + cc;
                    double coef = shd * (double)s_sw2[colL];
                    float d0 = (float)(coef * (double)accd[cc]);
                    float v = __fadd_rn(d0, s_b2[colL]);
                    (&vw.x)[e] = v;
                    lmin = fminf(lmin, v);
                    lmax = fmaxf(lmax, v);
                }
                size_t o = (size_t)rowd * C_DIM + bx * 128 + warpN * 64 + 40 + q6 * 4;
                *reinterpret_cast<float4*>(&out[o]) = vw;
            }
        }
    }

    red[tid] = lmax; __syncthreads();
    for (int s = 128; s > 0; s >>= 1) {
        if (tid < s) red[tid] = fmaxf(red[tid], red[tid + s]);
        __syncthreads();
    }
    if (tid == 0) atomicMaxF(&g_omax, red[0]);
    __syncthreads();
    red[tid] = lmin; __syncthreads();
    for (int s = 128; s > 0; s >>= 1) {
        if (tid < s) red[tid] = fminf(red[tid], red[tid + s]);
        __syncthreads();
    }
    if (tid == 0) atomicMinF(&g_omin, red[0]);
}

// ---------------- final asymmetric fake-quant of out (in place, x4) ----------------
__global__ void k_quant_out(float* __restrict__ out) {
    size_t i4 = (size_t)blockIdx.x * 256 + threadIdx.x;
    if (i4 >= (size_t)M_TOK * C_DIM / 4) return;
    float omn = fminf(g_omin, 0.f);
    float omx = fmaxf(g_omax, 0.f);
    float s = fmaxf(__fdiv_rn(__fsub_rn(omx, omn), 255.f), 1e-8f);
    float zp = rintf(__fdiv_rn(-omn, s));
    float4 v = reinterpret_cast<const float4*>(out)[i4];
    float q;
    q = fminf(fmaxf(__fadd_rn(rintf(__fdiv_rn(v.x, s)), zp), 0.f), 255.f);
    v.x = __fmul_rn(__fsub_rn(q, zp), s);
    q = fminf(fmaxf(__fadd_rn(rintf(__fdiv_rn(v.y, s)), zp), 0.f), 255.f);
    v.y = __fmul_rn(__fsub_rn(q, zp), s);
    q = fminf(fmaxf(__fadd_rn(rintf(__fdiv_rn(v.z, s)), zp), 0.f), 255.f);
    v.z = __fmul_rn(__fsub_rn(q, zp), s);
    q = fminf(fmaxf(__fadd_rn(rintf(__fdiv_rn(v.w, s)), zp), 0.f), 255.f);
    v.w = __fmul_rn(__fsub_rn(q, zp), s);
    reinterpret_cast<float4*>(out)[i4] = v;
}

// ---------------- launch ----------------
extern "C" void kernel_launch(void* const* d_in, const int* in_sizes, int n_in,
                              void* d_out, int out_size) {
    const float* x  = (const float*)d_in[0];
    const float* w1 = (const float*)d_in[1];
    const float* b1 = (const float*)d_in[2];
    const float* w2 = (const float*)d_in[3];
    const float* b2 = (const float*)d_in[4];
    float* out = (float*)d_out;

    cudaFuncSetAttribute(k_gemm1_tc, cudaFuncAttributeMaxDynamicSharedMemorySize, DYN_BYTES);
    cudaFuncSetAttribute(k_gemm2_mma, cudaFuncAttributeMaxDynamicSharedMemorySize, DYN_BYTES);

    k_init<<<3, 256>>>();
    k_stats<<<dim3(3, 64, 2), 256>>>(x, w1);
    k_scalars<<<1, 256>>>();

    size_t nx4 = (size_t)M_TOK * C_DIM / 4;
    k_quant_x<<<(unsigned)((nx4 + 255) / 256), 256>>>(x);
    k_quant_w<<<H_DIM + C_DIM, 256>>>(w1, w2);

    k_gemm1_tc<<<dim3(H_DIM / 128, (M_TOK + 127) / 128), 256, DYN_BYTES>>>(b1);

    size_t nh4 = (size_t)M_TOK * H_DIM / 4;
    k_flagq<<<(unsigned)((nh4 + 255) / 256), 256>>>();
    k_chain<<<2048, 256>>>(b1);
    k_fixq<<<512, 256>>>();

    k_gemm2_mma<<<dim3(C_DIM / 128, (M_TOK + 127) / 128), 256, DYN_BYTES>>>(b2, out);

    k_quant_out<<<(unsigned)((nx4 + 255) / 256), 256>>>(out);
}

// round 16
// speedup vs baseline: 1.0429x; 1.0429x over previous
#include <cuda_runtime.h>
#include <math.h>
#include <stdint.h>

#define M_TOK 12608
#define C_DIM 768
#define H_DIM 3072

// ---------------- scratch (device globals; no allocation allowed) ----------------
__device__ int8_t  g_qa[(size_t)M_TOK * C_DIM];
__device__ int8_t  g_qw1[(size_t)H_DIM * C_DIM];
__device__ int8_t  g_qw2[(size_t)C_DIM * H_DIM];
__device__ int8_t  g_qh[(size_t)M_TOK * H_DIM];
__device__ float   g_h[(size_t)M_TOK * H_DIM];      // g = gelu(h)
__device__ uint32_t g_wl[(size_t)M_TOK * H_DIM / 8];
__device__ unsigned int g_wlcnt;
__device__ float   g_xminC[C_DIM];
__device__ float   g_xmaxC[C_DIM];
__device__ float   g_w1cmax[C_DIM];
__device__ float   g_cs[C_DIM];
__device__ float   g_sw1[H_DIM];
__device__ int     g_colsum1[H_DIM];
__device__ float   g_sw2[C_DIM];
__device__ float   g_sx;
__device__ float   g_zp;
__device__ int     g_k128;
__device__ float   g_habs;   // approx (exact-h gelu max)
__device__ float   g_habs2;  // chain-exact (repaired candidates)
__device__ float   g_omin, g_omax;

// ---------------- atomic float min/max ----------------
__device__ __forceinline__ void atomicMaxF(float* a, float v) {
    if (v >= 0.f) atomicMax((int*)a, __float_as_int(v));
    else          atomicMin((unsigned int*)a, __float_as_uint(v));
}
__device__ __forceinline__ void atomicMinF(float* a, float v) {
    if (v >= 0.f) atomicMin((int*)a, __float_as_int(v));
    else          atomicMax((unsigned int*)a, __float_as_uint(v));
}

// ---------------- warp-level int8 MMA + ldmatrix + LDS (baseline PTX) ----------------
__device__ __forceinline__ void mma_s8(int* c, const uint32_t* a, const uint32_t* b) {
    asm volatile(
        "mma.sync.aligned.m16n8k32.row.col.s32.s8.s8.s32 "
        "{%0,%1,%2,%3}, {%4,%5,%6,%7}, {%8,%9}, {%0,%1,%2,%3};"
        : "+r"(c[0]), "+r"(c[1]), "+r"(c[2]), "+r"(c[3])
        : "r"(a[0]), "r"(a[1]), "r"(a[2]), "r"(a[3]), "r"(b[0]), "r"(b[1]));
}
__device__ __forceinline__ void ldsm_x4(uint32_t& r0, uint32_t& r1, uint32_t& r2,
                                        uint32_t& r3, uint32_t addr) {
    asm volatile("ldmatrix.sync.aligned.m8n8.x4.shared.b16 {%0,%1,%2,%3}, [%4];"
                 : "=r"(r0), "=r"(r1), "=r"(r2), "=r"(r3) : "r"(addr));
}
__device__ __forceinline__ uint4 lds128(uint32_t addr) {
    uint4 v;
    asm volatile("ld.shared.v4.u32 {%0,%1,%2,%3}, [%4];"
                 : "=r"(v.x), "=r"(v.y), "=r"(v.z), "=r"(v.w) : "r"(addr));
    return v;
}

// ---------------- cp.async helpers ----------------
__device__ __forceinline__ void cp16(uint32_t saddr, const void* g, uint32_t sz) {
    asm volatile("cp.async.cg.shared.global [%0], [%1], 16, %2;"
                 :: "r"(saddr), "l"(__cvta_generic_to_global(g)), "r"(sz));
}
__device__ __forceinline__ void cp_commit() {
    asm volatile("cp.async.commit_group;");
}
__device__ __forceinline__ void cp_wait2() {
    asm volatile("cp.async.wait_group 2;");
}

// ---------------- XLA f32 erf (ErfImpl32) ----------------
__device__ __forceinline__ float xla_erf(float x) {
    float w = fminf(fmaxf(x, -4.0f), 4.0f);
    float s = __fmul_rn(w, w);
    float num = -2.72614225801306e-10f;
    num = __fadd_rn(__fmul_rn(num, s),  2.77068142495902e-08f);
    num = __fadd_rn(__fmul_rn(num, s), -2.10102402082508e-06f);
    num = __fadd_rn(__fmul_rn(num, s), -5.69250639462346e-05f);
    num = __fadd_rn(__fmul_rn(num, s), -7.34990630326855e-04f);
    num = __fadd_rn(__fmul_rn(num, s), -2.95459980854025e-03f);
    num = __fadd_rn(__fmul_rn(num, s), -1.60960333262415e-02f);
    float den = -1.45660718464996e-05f;
    den = __fadd_rn(__fmul_rn(den, s), -2.13374055278905e-04f);
    den = __fadd_rn(__fmul_rn(den, s), -1.68282697438203e-03f);
    den = __fadd_rn(__fmul_rn(den, s), -7.37332916720468e-03f);
    den = __fadd_rn(__fmul_rn(den, s), -1.42647390514189e-02f);
    return __fdiv_rn(__fmul_rn(w, num), den);
}
__device__ __forceinline__ float xla_gelu(float x) {
    float u = __fdiv_rn(x, 1.4142135623730951f);
    float e = xla_erf(u);
    return __fmul_rn(__fmul_rn(x, __fadd_rn(e, 1.0f)), 0.5f);
}

// ---------------- init ----------------
__global__ void k_init() {
    int t = blockIdx.x * blockDim.x + threadIdx.x;
    if (t < C_DIM) {
        g_xminC[t]  = INFINITY;
        g_xmaxC[t]  = -INFINITY;
        g_w1cmax[t] = 0.f;
    }
    if (t == 0) {
        g_habs = 0.f; g_habs2 = 0.f; g_wlcnt = 0u;
        g_omin = INFINITY; g_omax = -INFINITY;
    }
}

// ---------------- merged per-channel stats: z=0 -> x min/max, z=1 -> |w1| max ----------------
__global__ void k_stats(const float* __restrict__ x, const float* __restrict__ w1) {
    int c = blockIdx.x * 256 + threadIdx.x;
    if (blockIdx.z == 0) {
        int m0 = blockIdx.y * 197;
        float mn = INFINITY, mx = -INFINITY;
        const float* p = x + (size_t)m0 * C_DIM + c;
        #pragma unroll 4
        for (int i = 0; i < 197; ++i) {
            float v = p[(size_t)i * C_DIM];
            mn = fminf(mn, v); mx = fmaxf(mx, v);
        }
        atomicMinF(&g_xminC[c], mn);
        atomicMaxF(&g_xmaxC[c], mx);
    } else {
        if (blockIdx.y >= 12) return;
        int h0 = blockIdx.y * 256;
        float mx = 0.f;
        const float* p = w1 + (size_t)h0 * C_DIM + c;
        #pragma unroll 4
        for (int i = 0; i < 256; ++i)
            mx = fmaxf(mx, fabsf(p[(size_t)i * C_DIM]));
        atomicMax((int*)&g_w1cmax[c], __float_as_int(mx));
    }
}

// ---------------- cs + activation scale/zp ----------------
__global__ void k_scalars() {
    __shared__ float smn[256], smx[256];
    int tid = threadIdx.x;
    const float LN2F = 0.6931471805599453f;
    float mn = INFINITY, mx = -INFINITY;
    for (int c = tid; c < C_DIM; c += 256) {
        float xlo = g_xminC[c], xhi = g_xmaxC[c];
        float gmax = fmaxf(fabsf(xlo), fabsf(xhi));
        float mw = g_w1cmax[c];
        float csr = __fdiv_rn(sqrtf(gmax), sqrtf(mw));
        float y = floorf(__fdiv_rn(logf(csr), LN2F));
        float p = exp2f(y);
        float cs = (__fsub_rn(csr, p) > __fsub_rn(__fmul_rn(2.f, p), csr)) ? 2.f * p : p;
        g_cs[c] = cs;
        mn = fminf(mn, __fdiv_rn(xlo, cs));
        mx = fmaxf(mx, __fdiv_rn(xhi, cs));
    }
    smn[tid] = mn; smx[tid] = mx;
    __syncthreads();
    for (int s = 128; s > 0; s >>= 1) {
        if (tid < s) {
            smn[tid] = fminf(smn[tid], smn[tid + s]);
            smx[tid] = fmaxf(smx[tid], smx[tid + s]);
        }
        __syncthreads();
    }
    if (tid == 0) {
        float xmn = fminf(smn[0], 0.f);
        float xmx = fmaxf(smx[0], 0.f);
        float s = fmaxf(__fdiv_rn(__fsub_rn(xmx, xmn), 255.f), 1e-8f);
        float zp = rintf(__fdiv_rn(-xmn, s));
        g_sx = s; g_zp = zp; g_k128 = 128 - (int)zp;
    }
}

// ---------------- quantize x -> s8 (q - 128), vectorized x4 ----------------
__global__ void k_quant_x(const float* __restrict__ x) {
    size_t i4 = (size_t)blockIdx.x * 256 + threadIdx.x;
    if (i4 >= (size_t)M_TOK * C_DIM / 4) return;
    int c = (int)((i4 * 4) % C_DIM);
    float s = g_sx, zp = g_zp;
    const float4 v = reinterpret_cast<const float4*>(x)[i4];
    char4 o;
    float t, q;
    t = __fdiv_rn(v.x, g_cs[c + 0]);
    q = fminf(fmaxf(__fadd_rn(rintf(__fdiv_rn(t, s)), zp), 0.f), 255.f);
    o.x = (int8_t)((int)q - 128);
    t = __fdiv_rn(v.y, g_cs[c + 1]);
    q = fminf(fmaxf(__fadd_rn(rintf(__fdiv_rn(t, s)), zp), 0.f), 255.f);
    o.y = (int8_t)((int)q - 128);
    t = __fdiv_rn(v.z, g_cs[c + 2]);
    q = fminf(fmaxf(__fadd_rn(rintf(__fdiv_rn(t, s)), zp), 0.f), 255.f);
    o.z = (int8_t)((int)q - 128);
    t = __fdiv_rn(v.w, g_cs[c + 3]);
    q = fminf(fmaxf(__fadd_rn(rintf(__fdiv_rn(t, s)), zp), 0.f), 255.f);
    o.w = (int8_t)((int)q - 128);
    reinterpret_cast<char4*>(g_qa)[i4] = o;
}

// ---------------- merged weight quant ----------------
__global__ void k_quant_w(const float* __restrict__ w1, const float* __restrict__ w2) {
    __shared__ float red[256];
    __shared__ int   redi[256];
    int tid = threadIdx.x;
    if (blockIdx.x < H_DIM) {
        int j = blockIdx.x;
        const float* row = w1 + (size_t)j * C_DIM;
        float mx = 0.f;
        for (int c = tid; c < C_DIM; c += 256)
            mx = fmaxf(mx, fabsf(__fmul_rn(row[c], g_cs[c])));
        red[tid] = mx; __syncthreads();
        for (int s = 128; s > 0; s >>= 1) {
            if (tid < s) red[tid] = fmaxf(red[tid], red[tid + s]);
            __syncthreads();
        }
        float sc = fmaxf(__fdiv_rn(red[0], 127.f), 1e-8f);
        __syncthreads();
        int csum = 0;
        for (int c = tid; c < C_DIM; c += 256) {
            float ws = __fmul_rn(row[c], g_cs[c]);
            float q = rintf(__fdiv_rn(ws, sc));
            q = fminf(fmaxf(q, -128.f), 127.f);
            int qi = (int)q;
            g_qw1[(size_t)j * C_DIM + c] = (int8_t)qi;
            csum += qi;
        }
        redi[tid] = csum; __syncthreads();
        for (int s = 128; s > 0; s >>= 1) {
            if (tid < s) redi[tid] += redi[tid + s];
            __syncthreads();
        }
        if (tid == 0) { g_colsum1[j] = redi[0]; g_sw1[j] = sc; }
    } else {
        int j = blockIdx.x - H_DIM;
        const float* row = w2 + (size_t)j * H_DIM;
        float mx = 0.f;
        for (int c = tid; c < H_DIM; c += 256)
            mx = fmaxf(mx, fabsf(row[c]));
        red[tid] = mx; __syncthreads();
        for (int s = 128; s > 0; s >>= 1) {
            if (tid < s) red[tid] = fmaxf(red[tid], red[tid + s]);
            __syncthreads();
        }
        float sc = fmaxf(__fdiv_rn(red[0], 127.f), 1e-8f);
        __syncthreads();
        for (int c = tid; c < H_DIM; c += 256) {
            float q = rintf(__fdiv_rn(row[c], sc));
            q = fminf(fmaxf(q, -128.f), 127.f);
            g_qw2[(size_t)j * H_DIM + c] = (int8_t)(int)q;
        }
        if (tid == 0) g_sw2[j] = sc;
    }
}

#define ROW_W 20            // smem row stride in words (64B data + 16B pad)
#define STG_WORDS (128 * ROW_W)
#define NSTAGE 4
#define DYN_BYTES (2 * NSTAGE * STG_WORDS * 4)   // 81920

// =====================================================================
// Hybrid chunk (R14/R11 exact): MMA cols 0..39 (tensor) + dp4a cols
// 40..63 (ALU), cc-outer dp4a with aw[16] preload. Bit-identical.
// =====================================================================
__device__ __forceinline__ void hyb_chunk(uint32_t aBase, uint32_t bBase,
                                          int warpM, int warpN, int lane,
                                          int rA, int cA, int rB, int cB,
                                          int (&acc)[2][5][4], int (&accd)[24]) {
    #pragma unroll
    for (int ks = 0; ks < 2; ++ks) {
        uint32_t a[2][4];
        #pragma unroll
        for (int mt = 0; mt < 2; ++mt) {
            uint32_t ad = aBase + 4u * (uint32_t)((warpM * 32 + mt * 16 + rA) * ROW_W + ks * 8 + cA);
            ldsm_x4(a[mt][0], a[mt][1], a[mt][2], a[mt][3], ad);
        }
        uint32_t b[6][2];
        #pragma unroll
        for (int np = 0; np < 3; ++np) {
            uint32_t bd = bBase + 4u * (uint32_t)((warpN * 64 + np * 16 + rB) * ROW_W + ks * 8 + cB);
            ldsm_x4(b[2 * np][0], b[2 * np][1], b[2 * np + 1][0], b[2 * np + 1][1], bd);
        }
        #pragma unroll
        for (int mt = 0; mt < 2; ++mt)
            #pragma unroll
            for (int nt = 0; nt < 5; ++nt)
                mma_s8(acc[mt][nt], a[mt], b[nt]);
    }
    uint32_t aw[16];
    {
        uint32_t ar = aBase + 4u * (uint32_t)((warpM * 32 + lane) * ROW_W);
        #pragma unroll
        for (int s = 0; s < 4; ++s) {
            uint4 v = lds128(ar + 16u * s);
            aw[4 * s] = v.x; aw[4 * s + 1] = v.y; aw[4 * s + 2] = v.z; aw[4 * s + 3] = v.w;
        }
    }
    #pragma unroll
    for (int cc = 0; cc < 24; ++cc) {
        uint32_t br = bBase + 4u * (uint32_t)((warpN * 64 + 40 + cc) * ROW_W);
        int a0 = accd[cc];
        #pragma unroll
        for (int s = 0; s < 4; ++s) {
            uint4 bv = lds128(br + 16u * s);
            a0 = __dp4a((int)aw[4 * s],     (int)bv.x, a0);
            a0 = __dp4a((int)aw[4 * s + 1], (int)bv.y, a0);
            a0 = __dp4a((int)aw[4 * s + 2], (int)bv.z, a0);
            a0 = __dp4a((int)aw[4 * s + 3], (int)bv.w, a0);
        }
        accd[cc] = a0;
    }
}

// =====================================================================
// GEMM1: hybrid IMMA+dp4a, 4-stage cp.async pipeline, occ=2 (R14).
// =====================================================================
__global__ __launch_bounds__(256, 2) void k_gemm1_tc(const float* __restrict__ b1) {
    extern __shared__ uint32_t dyn[];
    __shared__ float s_sw1[128], s_b1[128];
    __shared__ int   s_cs1[128];
    __shared__ float red[256];

    const int tid = threadIdx.x;
    const int wid = tid >> 5, lane = tid & 31;
    const int grp = lane >> 2, tg = lane & 3;
    const int warpM = wid & 3, warpN = wid >> 2;
    const int bx = blockIdx.x, by = blockIdx.y;
    const int iA = lane >> 3;
    const int rA = ((iA & 1) << 3) + (lane & 7), cA = (iA >> 1) << 2;
    const int rB = ((iA >> 1) << 3) + (lane & 7), cB = (iA & 1) << 2;

    if (tid < 128) {
        s_sw1[tid] = g_sw1[bx * 128 + tid];
        s_b1[tid]  = b1[bx * 128 + tid];
        s_cs1[tid] = g_colsum1[bx * 128 + tid];
    }

    int acc[2][5][4];
    int accd[24];
    #pragma unroll
    for (int mt = 0; mt < 2; ++mt)
        #pragma unroll
        for (int nt = 0; nt < 5; ++nt)
            #pragma unroll
            for (int r = 0; r < 4; ++r) acc[mt][nt][r] = 0;
    #pragma unroll
    for (int c = 0; c < 24; ++c) accd[c] = 0;

    const uint32_t dynAddr = (uint32_t)__cvta_generic_to_shared(dyn);
    const int srow = tid >> 1, shalf = tid & 1;
    const int growA = by * 128 + srow;
    const bool aval = (growA < M_TOK);
    const uint32_t asz = aval ? 16u : 0u;
    const int8_t* gA = g_qa + (size_t)(aval ? growA : 0) * C_DIM + shalf * 32;
    const int8_t* gB = g_qw1 + (size_t)(bx * 128 + srow) * C_DIM + shalf * 32;
    const uint32_t stOff = (uint32_t)((srow * ROW_W + shalf * 8) * 4);

    const int NCH = C_DIM / 64;  // 12
    #pragma unroll
    for (int s = 0; s < NSTAGE - 1; ++s) {
        uint32_t sa = dynAddr + (uint32_t)(s * STG_WORDS * 4) + stOff;
        uint32_t sb = dynAddr + (uint32_t)((NSTAGE + s) * STG_WORDS * 4) + stOff;
        const int8_t* ga = gA + s * 64;
        const int8_t* gb = gB + s * 64;
        cp16(sa, ga, asz); cp16(sa + 16, ga + 16, asz);
        cp16(sb, gb, 16u); cp16(sb + 16, gb + 16, 16u);
        cp_commit();
    }

    for (int kc = 0; kc < NCH; ++kc) {
        const int p = kc & (NSTAGE - 1);
        cp_wait2();
        __syncthreads();
        if (kc + NSTAGE - 1 < NCH) {
            const int q = (kc + NSTAGE - 1) & (NSTAGE - 1);
            uint32_t sa = dynAddr + (uint32_t)(q * STG_WORDS * 4) + stOff;
            uint32_t sb = dynAddr + (uint32_t)((NSTAGE + q) * STG_WORDS * 4) + stOff;
            const int8_t* ga = gA + (kc + NSTAGE - 1) * 64;
            const int8_t* gb = gB + (kc + NSTAGE - 1) * 64;
            cp16(sa, ga, asz); cp16(sa + 16, ga + 16, asz);
            cp16(sb, gb, 16u); cp16(sb + 16, gb + 16, 16u);
        }
        cp_commit();
        hyb_chunk(dynAddr + (uint32_t)(p * STG_WORDS * 4),
                  dynAddr + (uint32_t)((NSTAGE + p) * STG_WORDS * 4),
                  warpM, warpN, lane, rA, cA, rB, cB, acc, accd);
    }

    const double sxd = (double)g_sx;
    const int k128 = g_k128;
    float lmax = 0.f;
    #pragma unroll
    for (int mt = 0; mt < 2; ++mt) {
        int r0 = by * 128 + warpM * 32 + mt * 16 + grp;
        #pragma unroll
        for (int nt = 0; nt < 5; ++nt) {
            int colL = warpN * 64 + nt * 8 + tg * 2;
            size_t gcol = (size_t)bx * 128 + colL;
            double coef0 = sxd * (double)s_sw1[colL];
            double coef1 = sxd * (double)s_sw1[colL + 1];
            int corr0 = k128 * s_cs1[colL];
            int corr1 = k128 * s_cs1[colL + 1];
            double bb0 = (double)s_b1[colL], bb1 = (double)s_b1[colL + 1];
            #pragma unroll
            for (int hh = 0; hh < 2; ++hh) {
                int row = r0 + hh * 8;
                if (row < M_TOK) {
                    float h0 = (float)(coef0 * (double)(acc[mt][nt][hh * 2] + corr0) + bb0);
                    float h1 = (float)(coef1 * (double)(acc[mt][nt][hh * 2 + 1] + corr1) + bb1);
                    float g0 = xla_gelu(h0);
                    float g1 = xla_gelu(h1);
                    size_t o = (size_t)row * H_DIM + gcol;
                    g_h[o] = g0; g_h[o + 1] = g1;
                    lmax = fmaxf(lmax, fmaxf(fabsf(g0), fabsf(g1)));
                }
            }
        }
    }
    {
        int rowd = by * 128 + warpM * 32 + lane;
        if (rowd < M_TOK) {
            #pragma unroll
            for (int q6 = 0; q6 < 6; ++q6) {
                float4 gw;
                #pragma unroll
                for (int e = 0; e < 4; ++e) {
                    int cc = q6 * 4 + e;
                    int colL = warpN * 64 + 40 + cc;
                    double coef = sxd * (double)s_sw1[colL];
                    int corr = k128 * s_cs1[colL];
                    double bb = (double)s_b1[colL];
                    float h = (float)(coef * (double)(accd[cc] + corr) + bb);
                    float g = xla_gelu(h);
                    (&gw.x)[e] = g;
                    lmax = fmaxf(lmax, fabsf(g));
                }
                size_t o = (size_t)rowd * H_DIM + bx * 128 + warpN * 64 + 40 + q6 * 4;
                *reinterpret_cast<float4*>(&g_h[o]) = gw;
            }
        }
    }
    red[tid] = lmax; __syncthreads();
    for (int s = 128; s > 0; s >>= 1) {
        if (tid < s) red[tid] = fmaxf(red[tid], red[tid + s]);
        __syncthreads();
    }
    if (tid == 0) atomicMaxF(&g_habs, red[0]);
}

// =====================================================================
// Fused flag + provisional quant, warp-aggregated worklist allocation.
// =====================================================================
__global__ void k_flagq() {
    size_t i4 = (size_t)blockIdx.x * 256 + threadIdx.x;
    if (i4 >= (size_t)M_TOK * H_DIM / 4) return;
    const float4 g4 = reinterpret_cast<const float4*>(g_h)[i4];
    float gv[4] = { g4.x, g4.y, g4.z, g4.w };
    float habs = g_habs;
    float sh = fmaxf(__fdiv_rn(habs, 127.f), 1e-8f);
    float taumax = fmaxf(habs, 2.f) * 1.6e-5f;
    const unsigned int cap = (unsigned int)((size_t)M_TOK * H_DIM / 8);
    char4 o;
    #pragma unroll
    for (int t = 0; t < 4; ++t) {
        float g = gv[t];
        float r = __fdiv_rn(g, sh);
        float q = fminf(fmaxf(rintf(r), -128.f), 127.f);
        ((int8_t*)&o)[t] = (int8_t)(int)q;
        float hb = fmaxf(fabsf(g) + 0.25f, 3.0f);
        float tau = hb * 8e-6f + fabsf(g) * 4e-5f + 1e-6f;
        bool cand = fabsf(g) > habs - 2.f * taumax;
        float d = fabsf(r - rintf(r));
        bool flag = (fabsf(d - 0.5f) * sh < tau) || cand;
        // warp-aggregated worklist append (order-free)
        unsigned int mask = __ballot_sync(0xFFFFFFFFu, flag);
        if (mask) {
            int lane = threadIdx.x & 31;
            int leader = __ffs(mask) - 1;
            unsigned int base = 0;
            if (lane == leader)
                base = atomicAdd(&g_wlcnt, (unsigned int)__popc(mask));
            base = __shfl_sync(0xFFFFFFFFu, base, leader);
            if (flag) {
                unsigned int pos = base + (unsigned int)__popc(mask & ((1u << lane) - 1u));
                if (pos < cap) g_wl[pos] = (uint32_t)(i4 * 4 + t);
            }
        }
    }
    reinterpret_cast<char4*>(g_qh)[i4] = o;
}

// =====================================================================
// Chain-repair pass.
// =====================================================================
__global__ void k_chain(const float* __restrict__ b1) {
    unsigned int total = g_wlcnt;
    unsigned int cap = (unsigned int)((size_t)M_TOK * H_DIM / 8);
    if (total > cap) total = cap;
    const float sx = g_sx;
    const float k128f = (float)g_k128;
    float wmax = 0.f;
    for (unsigned int w = blockIdx.x * blockDim.x + threadIdx.x;
         w < total; w += gridDim.x * blockDim.x) {
        uint32_t idx = g_wl[w];
        int row = (int)(idx / H_DIM);
        int col = (int)(idx % H_DIM);
        const int8_t* ap = g_qa + (size_t)row * C_DIM;
        const int8_t* bp = g_qw1 + (size_t)col * C_DIM;
        const float sw = g_sw1[col];
        float acc = 0.f;
        for (int k = 0; k < C_DIM; k += 8) {
            int2 av = *reinterpret_cast<const int2*>(ap + k);
            int2 bv = *reinterpret_cast<const int2*>(bp + k);
            #pragma unroll
            for (int t = 0; t < 4; ++t) {
                float a = __fmul_rn((float)(int)(int8_t)(av.x >> (8 * t)) + k128f, sx);
                float b = __fmul_rn((float)(int)(int8_t)(bv.x >> (8 * t)), sw);
                acc = __fmaf_rn(a, b, acc);
            }
            #pragma unroll
            for (int t = 0; t < 4; ++t) {
                float a = __fmul_rn((float)(int)(int8_t)(av.y >> (8 * t)) + k128f, sx);
                float b = __fmul_rn((float)(int)(int8_t)(bv.y >> (8 * t)), sw);
                acc = __fmaf_rn(a, b, acc);
            }
        }
        float hv = __fadd_rn(acc, b1[col]);
        float gv = xla_gelu(hv);
        g_h[idx] = gv;
        wmax = fmaxf(wmax, fabsf(gv));
    }
    #pragma unroll
    for (int o = 16; o > 0; o >>= 1)
        wmax = fmaxf(wmax, __shfl_down_sync(0xFFFFFFFFu, wmax, o));
    if ((threadIdx.x & 31) == 0 && wmax > 0.f) atomicMaxF(&g_habs2, wmax);
}

// ---------------- re-quantize flagged elements with final sh2 ----------------
__global__ void k_fixq() {
    unsigned int total = g_wlcnt;
    unsigned int cap = (unsigned int)((size_t)M_TOK * H_DIM / 8);
    if (total > cap) total = cap;
    float sh = fmaxf(__fdiv_rn(g_habs2, 127.f), 1e-8f);
    for (unsigned int w = blockIdx.x * blockDim.x + threadIdx.x;
         w < total; w += gridDim.x * blockDim.x) {
        uint32_t idx = g_wl[w];
        float g = g_h[idx];
        float q = fminf(fmaxf(rintf(__fdiv_rn(g, sh)), -128.f), 127.f);
        g_qh[idx] = (int8_t)(int)q;
    }
}

// =====================================================================
// GEMM2: hybrid IMMA+dp4a, 4-stage cp.async pipeline, occ=2 (R14).
// =====================================================================
__global__ __launch_bounds__(256, 2) void k_gemm2_mma(const float* __restrict__ b2,
                                                      float* __restrict__ out) {
    extern __shared__ uint32_t dyn[];
    __shared__ float s_sw2[128], s_b2[128];
    __shared__ float red[256];

    const int tid = threadIdx.x;
    const int wid = tid >> 5, lane = tid & 31;
    const int grp = lane >> 2, tg = lane & 3;
    const int warpM = wid & 3, warpN = wid >> 2;
    const int bx = blockIdx.x, by = blockIdx.y;
    const int iA = lane >> 3;
    const int rA = ((iA & 1) << 3) + (lane & 7), cA = (iA >> 1) << 2;
    const int rB = ((iA >> 1) << 3) + (lane & 7), cB = (iA & 1) << 2;

    if (tid < 128) {
        s_sw2[tid] = g_sw2[bx * 128 + tid];
        s_b2[tid]  = b2[bx * 128 + tid];
    }

    int acc[2][5][4];
    int accd[24];
    #pragma unroll
    for (int mt = 0; mt < 2; ++mt)
        #pragma unroll
        for (int nt = 0; nt < 5; ++nt)
            #pragma unroll
            for (int r = 0; r < 4; ++r) acc[mt][nt][r] = 0;
    #pragma unroll
    for (int c = 0; c < 24; ++c) accd[c] = 0;

    const uint32_t dynAddr = (uint32_t)__cvta_generic_to_shared(dyn);
    const int srow = tid >> 1, shalf = tid & 1;
    const int growA = by * 128 + srow;
    const bool aval = (growA < M_TOK);
    const uint32_t asz = aval ? 16u : 0u;
    const int8_t* gA = g_qh + (size_t)(aval ? growA : 0) * H_DIM + shalf * 32;
    const int8_t* gB = g_qw2 + (size_t)(bx * 128 + srow) * H_DIM + shalf * 32;
    const uint32_t stOff = (uint32_t)((srow * ROW_W + shalf * 8) * 4);

    const int NCH = H_DIM / 64;  // 48
    #pragma unroll
    for (int s = 0; s < NSTAGE - 1; ++s) {
        uint32_t sa = dynAddr + (uint32_t)(s * STG_WORDS * 4) + stOff;
        uint32_t sb = dynAddr + (uint32_t)((NSTAGE + s) * STG_WORDS * 4) + stOff;
        const int8_t* ga = gA + s * 64;
        const int8_t* gb = gB + s * 64;
        cp16(sa, ga, asz); cp16(sa + 16, ga + 16, asz);
        cp16(sb, gb, 16u); cp16(sb + 16, gb + 16, 16u);
        cp_commit();
    }

    for (int kc = 0; kc < NCH; ++kc) {
        const int p = kc & (NSTAGE - 1);
        cp_wait2();
        __syncthreads();
        if (kc + NSTAGE - 1 < NCH) {
            const int q = (kc + NSTAGE - 1) & (NSTAGE - 1);
            uint32_t sa = dynAddr + (uint32_t)(q * STG_WORDS * 4) + stOff;
            uint32_t sb = dynAddr + (uint32_t)((NSTAGE + q) * STG_WORDS * 4) + stOff;
            const int8_t* ga = gA + (kc + NSTAGE - 1) * 64;
            const int8_t* gb = gB + (kc + NSTAGE - 1) * 64;
            cp16(sa, ga, asz); cp16(sa + 16, ga + 16, asz);
            cp16(sb, gb, 16u); cp16(sb + 16, gb + 16, 16u);
        }
        cp_commit();
        hyb_chunk(dynAddr + (uint32_t)(p * STG_WORDS * 4),
                  dynAddr + (uint32_t)((NSTAGE + p) * STG_WORDS * 4),
                  warpM, warpN, lane, rA, cA, rB, cB, acc, accd);
    }

    const double shd = (double)fmaxf(__fdiv_rn(g_habs2, 127.f), 1e-8f);
    float lmin = INFINITY, lmax = -INFINITY;
    #pragma unroll
    for (int mt = 0; mt < 2; ++mt) {
        int r0 = by * 128 + warpM * 32 + mt * 16 + grp;
        #pragma unroll
        for (int nt = 0; nt < 5; ++nt) {
            int colL = warpN * 64 + nt * 8 + tg * 2;
            double coef0 = shd * (double)s_sw2[colL];
            double coef1 = shd * (double)s_sw2[colL + 1];
            float bb0 = s_b2[colL], bb1 = s_b2[colL + 1];
            size_t gcol = (size_t)bx * 128 + colL;
            #pragma unroll
            for (int h = 0; h < 2; ++h) {
                int row = r0 + h * 8;
                if (row < M_TOK) {
                    float d0 = (float)(coef0 * (double)acc[mt][nt][h * 2]);
                    float d1 = (float)(coef1 * (double)acc[mt][nt][h * 2 + 1]);
                    float v0 = __fadd_rn(d0, bb0);
                    float v1 = __fadd_rn(d1, bb1);
                    out[(size_t)row * C_DIM + gcol]     = v0;
                    out[(size_t)row * C_DIM + gcol + 1] = v1;
                    lmin = fminf(lmin, fminf(v0, v1));
                    lmax = fmaxf(lmax, fmaxf(v0, v1));
                }
            }
        }
    }
    {
        int rowd = by * 128 + warpM * 32 + lane;
        if (rowd < M_TOK) {
            #pragma unroll
            for (int q6 = 0; q6 < 6; ++q6) {
                float4 vw;
                #pragma unroll
                for (int e = 0; e < 4; ++e) {
                    int cc = q6 * 4 + e;
                    int colL = warpN * 64 + 40 + cc;
                    double coef = shd * (double)s_sw2[colL];
                    float d0 = (float)(coef * (double)accd[cc]);
                    float v = __fadd_rn(d0, s_b2[colL]);
                    (&vw.x)[e] = v;
                    lmin = fminf(lmin, v);
                    lmax = fmaxf(lmax, v);
                }
                size_t o = (size_t)rowd * C_DIM + bx * 128 + warpN * 64 + 40 + q6 * 4;
                *reinterpret_cast<float4*>(&out[o]) = vw;
            }
        }
    }

    red[tid] = lmax; __syncthreads();
    for (int s = 128; s > 0; s >>= 1) {
        if (tid < s) red[tid] = fmaxf(red[tid], red[tid + s]);
        __syncthreads();
    }
    if (tid == 0) atomicMaxF(&g_omax, red[0]);
    __syncthreads();
    red[tid] = lmin; __syncthreads();
    for (int s = 128; s > 0; s >>= 1) {
        if (tid < s) red[tid] = fminf(red[tid], red[tid + s]);
        __syncthreads();
    }
    if (tid == 0) atomicMinF(&g_omin, red[0]);
}

// ---------------- final asymmetric fake-quant of out (in place, x4) ----------------
__global__ void k_quant_out(float* __restrict__ out) {
    size_t i4 = (size_t)blockIdx.x * 256 + threadIdx.x;
    if (i4 >= (size_t)M_TOK * C_DIM / 4) return;
    float omn = fminf(g_omin, 0.f);
    float omx = fmaxf(g_omax, 0.f);
    float s = fmaxf(__fdiv_rn(__fsub_rn(omx, omn), 255.f), 1e-8f);
    float zp = rintf(__fdiv_rn(-omn, s));
    float4 v = reinterpret_cast<const float4*>(out)[i4];
    float q;
    q = fminf(fmaxf(__fadd_rn(rintf(__fdiv_rn(v.x, s)), zp), 0.f), 255.f);
    v.x = __fmul_rn(__fsub_rn(q, zp), s);
    q = fminf(fmaxf(__fadd_rn(rintf(__fdiv_rn(v.y, s)), zp), 0.f), 255.f);
    v.y = __fmul_rn(__fsub_rn(q, zp), s);
    q = fminf(fmaxf(__fadd_rn(rintf(__fdiv_rn(v.z, s)), zp), 0.f), 255.f);
    v.z = __fmul_rn(__fsub_rn(q, zp), s);
    q = fminf(fmaxf(__fadd_rn(rintf(__fdiv_rn(v.w, s)), zp), 0.f), 255.f);
    v.w = __fmul_rn(__fsub_rn(q, zp), s);
    reinterpret_cast<float4*>(out)[i4] = v;
}

// ---------------- launch ----------------
extern "C" void kernel_launch(void* const* d_in, const int* in_sizes, int n_in,
                              void* d_out, int out_size) {
    const float* x  = (const float*)d_in[0];
    const float* w1 = (const float*)d_in[1];
    const float* b1 = (const float*)d_in[2];
    const float* w2 = (const float*)d_in[3];
    const float* b2 = (const float*)d_in[4];
    float* out = (float*)d_out;

    cudaFuncSetAttribute(k_gemm1_tc, cudaFuncAttributeMaxDynamicSharedMemorySize, DYN_BYTES);
    cudaFuncSetAttribute(k_gemm2_mma, cudaFuncAttributeMaxDynamicSharedMemorySize, DYN_BYTES);

    k_init<<<3, 256>>>();
    k_stats<<<dim3(3, 64, 2), 256>>>(x, w1);
    k_scalars<<<1, 256>>>();

    size_t nx4 = (size_t)M_TOK * C_DIM / 4;
    k_quant_x<<<(unsigned)((nx4 + 255) / 256), 256>>>(x);
    k_quant_w<<<H_DIM + C_DIM, 256>>>(w1, w2);

    k_gemm1_tc<<<dim3(H_DIM / 128, (M_TOK + 127) / 128), 256, DYN_BYTES>>>(b1);

    size_t nh4 = (size_t)M_TOK * H_DIM / 4;
    k_flagq<<<(unsigned)((nh4 + 255) / 256), 256>>>();
    k_chain<<<2048, 256>>>(b1);
    k_fixq<<<512, 256>>>();

    k_gemm2_mma<<<dim3(C_DIM / 128, (M_TOK + 127) / 128), 256, DYN_BYTES>>>(b2, out);

    k_quant_out<<<(unsigned)((nx4 + 255) / 256), 256>>>(out);
}